// round 1
// baseline (speedup 1.0000x reference)
#include <cuda_runtime.h>

// CRF NLL: forward log-partition scan + gold score.
// B=512 batches, S=512 steps, T=64 tags (last two are START/STOP).
// Grid: one block per batch, 64 threads (one per "to" tag).

constexpr int Bb = 512;
constexpr int Ss = 512;
constexpr int Tt = 64;
constexpr int START = Tt - 2;
constexpr int STOP  = Tt - 1;

__device__ float g_partial[Bb];

__global__ __launch_bounds__(Tt) void crf_batch_kernel(
    const float* __restrict__ feats,
    const unsigned char* __restrict__ mask8,
    const int* __restrict__ tags,
    const float* __restrict__ trans)
{
    const int b  = blockIdx.x;
    const int to = threadIdx.x;   // 0..63

    __shared__ float4 pe4[2][Tt / 4];   // exp(part - mu), double-buffered
    __shared__ float  bc[4];            // ring of thread-0 partition values (shift broadcast)
    __shared__ float  red[Tt];
    __shared__ int    ired[Tt];
    __shared__ int    shL;

    // ---- mask layout probe (bool->uint8 vs int32) + sequence length ----
    // mask is prefix-contiguous with L >= S/2, so a real uint8 mask starts 1,1,1,1;
    // an int32 "1" viewed as bytes is 1,0,0,0.
    const int* mask32 = reinterpret_cast<const int*>(mask8);
    const bool is32 = (mask8[0] == 1 && mask8[1] == 0 && mask8[2] == 0 && mask8[3] == 0);

    int cnt = 0;
    #pragma unroll
    for (int k = 0; k < Ss / Tt; ++k) {
        int s  = to + k * Tt;
        int mv = is32 ? mask32[b * Ss + s] : (int)mask8[b * Ss + s];
        cnt += (mv != 0);
    }
    ired[to] = cnt;
    __syncthreads();
    if (to == 0) {
        int L = 0;
        #pragma unroll
        for (int i = 0; i < Tt; ++i) L += ired[i];
        shL = L;
    }
    __syncthreads();
    const int L = shL;

    const float* fb = feats + (size_t)b * Ss * Tt;
    const int*   tg = tags + b * Ss;

    // ---- gold path score (parallel over positions, deterministic reduce) ----
    float gsum = 0.f;
    for (int s = to; s < L; s += Tt) {
        int t1 = tg[s];
        int t0 = (s == 0) ? START : tg[s - 1];
        gsum += fb[s * Tt + t1] + trans[t0 * Tt + t1];
    }
    red[to] = gsum;
    __syncthreads();
    float gold = 0.f;
    if (to == 0) {
        #pragma unroll
        for (int i = 0; i < Tt; ++i) gold += red[i];
        gold += trans[tg[L - 1] * Tt + STOP];
    }
    __syncthreads();

    // ---- E column (exp of transitions into tag 'to') in registers ----
    float E[Tt];
    #pragma unroll
    for (int f = 0; f < Tt; ++f) E[f] = __expf(trans[f * Tt + to]);

    // ---- init: part_0[to] = feats[b,0,to] + trans[START, to] ----
    float part = fb[to] + trans[START * Tt + to];
    if (to == 0) bc[0] = part;
    __syncthreads();
    const float mu0 = bc[0];
    {
        float* pw = reinterpret_cast<float*>(&pe4[0][0]);
        pw[to] = __expf(part - mu0);
    }
    float mu_carry = mu0;   // shift encoded in the pe buffer we'll read next
    __syncthreads();

    float fnext = (L > 1) ? fb[Tt + to] : 0.f;

    // ---- forward scan: one barrier per step ----
    for (int s = 1; s < L; ++s) {
        const float f = fnext;
        if (s + 1 < L) fnext = fb[(s + 1) * Tt + to];  // prefetch next step

        const float mu_pe = bc[(s - 1) & 3];           // part_{s-1}[0] : shift for pe we write
        const float4* p4 = &pe4[(s - 1) & 1][0];

        float a0 = 0.f, a1 = 0.f, a2 = 0.f, a3 = 0.f;
        #pragma unroll
        for (int j = 0; j < Tt / 4; ++j) {
            float4 p = p4[j];
            a0 = fmaf(p.x, E[4 * j + 0], a0);
            a1 = fmaf(p.y, E[4 * j + 1], a1);
            a2 = fmaf(p.z, E[4 * j + 2], a2);
            a3 = fmaf(p.w, E[4 * j + 3], a3);
        }
        const float acc  = (a0 + a1) + (a2 + a3);
        const float newp = f + mu_carry + __logf(acc);

        if (to == 0) bc[s & 3] = newp;
        {
            float* pw = reinterpret_cast<float*>(&pe4[s & 1][0]);
            pw[to] = __expf(newp - mu_pe);
        }
        part     = newp;
        mu_carry = mu_pe;
        __syncthreads();
    }

    // ---- final transition to STOP: logsumexp_from(part[from] + trans[from,STOP]) ----
    const float mu_f = bc[(L - 1) & 3];   // part_{L-1}[0] (for L==1 this is bc[0])
    const float c = __expf(part - mu_f) * __expf(trans[to * Tt + STOP]);
    red[to] = c;
    __syncthreads();
    if (to == 0) {
        float ssum = 0.f;
        #pragma unroll
        for (int i = 0; i < Tt; ++i) ssum += red[i];
        const float fwd = mu_f + __logf(ssum);
        g_partial[b] = fwd - gold;
    }
}

__global__ void finalize_kernel(float* __restrict__ out)
{
    __shared__ float sh[Bb];
    const int t = threadIdx.x;
    sh[t] = g_partial[t];
    __syncthreads();
    #pragma unroll
    for (int off = Bb / 2; off > 0; off >>= 1) {
        if (t < off) sh[t] += sh[t + off];
        __syncthreads();
    }
    if (t == 0) out[0] = sh[0];
}

extern "C" void kernel_launch(void* const* d_in, const int* in_sizes, int n_in,
                              void* d_out, int out_size)
{
    (void)in_sizes; (void)n_in; (void)out_size;
    const float*         feats = (const float*)d_in[0];
    const unsigned char* mask  = (const unsigned char*)d_in[1];
    const int*           tags  = (const int*)d_in[2];
    const float*         trans = (const float*)d_in[3];

    crf_batch_kernel<<<Bb, Tt>>>(feats, mask, tags, trans);
    finalize_kernel<<<1, Bb>>>((float*)d_out);
}